// round 1
// baseline (speedup 1.0000x reference)
#include <cuda_runtime.h>
#include <math.h>

// SphericalFilter: out[p,h] = sum_k Y[p,k] * W[h,k] + b[h]
// P = 131072 pixels, H = 1024, K = 129 (m = -64..64, shift=1)
//
// Fused kernel: each CTA computes a 128(pixel) x 128(h) tile of the output.
// Phase 1: 128 threads compute the 129 harmonics for 128 pixels into smem
//          (k-major), while all 256 threads also load the 128x129 W tile
//          (coalesced global read, transposed store to k-major smem).
// Phase 2: classic register-blocked SGEMM, 8x8 micro-tile per thread,
//          full K resident in smem.

#define NK 129
#define TILE_P 128
#define TILE_H 128
#define NTHREADS 256
#define B_STRIDE 132   // padded row (floats) for W tile, 16B-aligned rows
#define A_STRIDE 129   // row stride for Y tile (bank-stride 1, conflict-free)

// smem layout: Bsh first (16B aligned), then Ash
#define BSH_FLOATS (NK * B_STRIDE)          // 17028
#define ASH_FLOATS (NK * A_STRIDE)          // 16641
#define SMEM_BYTES ((BSH_FLOATS + ASH_FLOATS) * 4)  // 134676

__global__ __launch_bounds__(NTHREADS, 1)
void sph_filter_kernel(const float* __restrict__ x,
                       const float* __restrict__ W,
                       const float* __restrict__ bvec,
                       float* __restrict__ out,
                       int H) {
    extern __shared__ float smem[];
    float* Bsh = smem;                 // [NK][B_STRIDE]  W tile, k-major
    float* Ash = smem + BSH_FLOATS;    // [NK][A_STRIDE]  Y tile, k-major

    const int tid   = threadIdx.x;
    const int ptile = blockIdx.x * TILE_P;
    const int hbase = blockIdx.y * TILE_H;

    // ---- load W tile (coalesced global, transposed store) ----
    for (int i = tid; i < TILE_H * NK; i += NTHREADS) {
        int h = i / NK;
        int k = i - h * NK;
        Bsh[k * B_STRIDE + h] = W[(size_t)(hbase + h) * NK + k];
    }

    // ---- compute Y for 128 pixels (threads 0..127, one pixel each) ----
    if (tid < TILE_P) {
        int p = ptile + tid;
        float theta = x[2 * p + 0];
        float phi   = x[2 * p + 1];
        float ct = cosf(phi);
        float st = sqrtf(fmaxf(1.0f - ct * ct, 0.0f));
        float pmm = 0.28209479177387814f;          // sqrt(1/(4*pi))
        // m = 0: y0 = sqrt(3) * ct * pmm
        Ash[64 * A_STRIDE + tid] = 1.7320508075688772f * ct * pmm;
        float cth = cosf(theta), sth = sinf(theta);
        float cm = 1.0f, sm = 0.0f;                // cos(m*theta), sin(m*theta)
        #pragma unroll 1
        for (int m = 1; m <= 64; ++m) {
            // Pbar_m^m = -sqrt((2m+1)/(2m)) * st * Pbar_{m-1}^{m-1}
            pmm *= -sqrtf((2.0f * m + 1.0f) / (2.0f * m)) * st;
            // rotate (cos(m t), sin(m t))
            float c2 = cm * cth - sm * sth;
            float s2 = sm * cth + cm * sth;
            cm = c2; sm = s2;
            // ybar = sqrt(2m+3) * ct * pmm  (l = m+1 climb, shift=1)
            float v = sqrtf(2.0f * m + 3.0f) * ct * pmm;
            v = (m & 1) ? (-1.41421356237309515f * v)
                        : ( 1.41421356237309515f * v);
            Ash[(64 + m) * A_STRIDE + tid] = v * cm;   // cos branch
            Ash[(64 - m) * A_STRIDE + tid] = v * sm;   // sin branch
        }
    }
    __syncthreads();

    // ---- register-blocked GEMM: 8 pixels x 8 h per thread ----
    const int tx = tid & 15;    // pixel group: pixels tx + 16*j
    const int ty = tid >> 4;    // h group: h = hbase + ty*8 + i (contiguous 8)

    float acc[8][8];
    #pragma unroll
    for (int j = 0; j < 8; ++j)
        #pragma unroll
        for (int i = 0; i < 8; ++i) acc[j][i] = 0.0f;

    #pragma unroll 3
    for (int k = 0; k < NK; ++k) {
        const float* br = &Bsh[k * B_STRIDE + ty * 8];
        float4 b0 = *(const float4*)(br);
        float4 b1 = *(const float4*)(br + 4);
        float bv[8] = {b0.x, b0.y, b0.z, b0.w, b1.x, b1.y, b1.z, b1.w};
        float a[8];
        const float* ar = &Ash[k * A_STRIDE + tx];
        #pragma unroll
        for (int j = 0; j < 8; ++j) a[j] = ar[16 * j];
        #pragma unroll
        for (int j = 0; j < 8; ++j)
            #pragma unroll
            for (int i = 0; i < 8; ++i)
                acc[j][i] = fmaf(a[j], bv[i], acc[j][i]);
    }

    // ---- epilogue: add bias, vectorized store (h contiguous per thread) ----
    const int h0 = hbase + ty * 8;
    float4 bb0 = *(const float4*)&bvec[h0];
    float4 bb1 = *(const float4*)&bvec[h0 + 4];
    #pragma unroll
    for (int j = 0; j < 8; ++j) {
        int p = ptile + tx + 16 * j;
        float4 o0 = make_float4(acc[j][0] + bb0.x, acc[j][1] + bb0.y,
                                acc[j][2] + bb0.z, acc[j][3] + bb0.w);
        float4 o1 = make_float4(acc[j][4] + bb1.x, acc[j][5] + bb1.y,
                                acc[j][6] + bb1.z, acc[j][7] + bb1.w);
        float4* op = (float4*)&out[(size_t)p * H + h0];
        op[0] = o0;
        op[1] = o1;
    }
}

extern "C" void kernel_launch(void* const* d_in, const int* in_sizes, int n_in,
                              void* d_out, int out_size) {
    const float* x = (const float*)d_in[0];   // (4,128,256,1,2)
    const float* W = (const float*)d_in[1];   // (1024,129)
    const float* b = (const float*)d_in[2];   // (1024,)
    float* out = (float*)d_out;               // (4,128,256,1,1024)

    const int P = in_sizes[0] / 2;            // 131072
    const int H = in_sizes[2];                // 1024

    cudaFuncSetAttribute(sph_filter_kernel,
                         cudaFuncAttributeMaxDynamicSharedMemorySize,
                         SMEM_BYTES);

    dim3 grid(P / TILE_P, H / TILE_H);        // (1024, 8)
    sph_filter_kernel<<<grid, NTHREADS, SMEM_BYTES>>>(x, W, b, out, H);
}

// round 3
// speedup vs baseline: 3.0222x; 3.0222x over previous
#include <cuda_runtime.h>
#include <cstdint>
#include <math.h>

// SphericalFilter via mma.sync.m16n8k8 tf32 (plain-target tensor path; the
// harness PTX target is compute_103 without the 'a' feature suffix, so
// tcgen05 is unavailable).
//
// out[p,h] = sum_k Y[p,k] * W[h,k] + b[h];  P=131072, H=1024, K=129 (pad 136)
//
// wfrag_kernel: reorder W into the mma.m16n8k8 B-fragment layout (tf32) in a
//   __device__ global (557KB, L2-resident; read by every CTA).
// sph_mma_kernel: one CTA = 128 pixels x full H. Y computed once into smem,
//   pre-swizzled into the exact A-fragment layout (LDS.128 = 4 A-regs).
//   Loop 8 h-tiles x 17 k-chunks x 16 mma per warp (64x32 warptile); B frags
//   via coalesced LDG.64 from the global frag array with 1-step prefetch.

#define NK 129
#define NKPAD 136
#define NKC 17            // k-chunks of 8
#define H_TOT 1024
#define TILE_P 128
#define NTHREADS 256
#define NTILES_H 8        // 1024 / 128

#define AFRAG_FLOATS (8 * NKC * 32 * 4)   // 17408 floats = 69632 B
#define SMEM_BYTES (AFRAG_FLOATS * 4)

__device__ float Wfrag[128 * NKC * 32 * 2];   // [ntile][kc][lane][breg]

// ---------------- helpers ----------------
__device__ __forceinline__ float tf32r(float v) {
    uint32_t t;
    asm("cvt.rn.tf32.f32 %0, %1;" : "=r"(t) : "f"(v));
    return __uint_as_float(t);
}

// float index of A-fragment element (row, k) in smem.
// chunk = ((mtile*17 + kc)*32 + c*8 + r4); within chunk: reg = half + 2*khalf.
__device__ __forceinline__ int a_off(int row, int k) {
    int mt = row >> 4, half = (row >> 3) & 1, r4 = row & 7;
    int kc = k >> 3, khalf = (k >> 2) & 1, c = k & 3;
    return ((mt * NKC + kc) * 32 + c * 8 + r4) * 4 + half + 2 * khalf;
}

__device__ __forceinline__ void mma8(float4 a, float2 b, float* c) {
    asm volatile(
        "mma.sync.aligned.m16n8k8.row.col.f32.tf32.tf32.f32 "
        "{%0,%1,%2,%3}, {%4,%5,%6,%7}, {%8,%9}, {%0,%1,%2,%3};"
        : "+f"(c[0]), "+f"(c[1]), "+f"(c[2]), "+f"(c[3])
        : "r"(__float_as_uint(a.x)), "r"(__float_as_uint(a.y)),
          "r"(__float_as_uint(a.z)), "r"(__float_as_uint(a.w)),
          "r"(__float_as_uint(b.x)), "r"(__float_as_uint(b.y)));
}

// ---------------- W -> B-fragment reorder ----------------
__global__ void wfrag_kernel(const float* __restrict__ W) {
    int idx = blockIdx.x * blockDim.x + threadIdx.x;
    if (idx >= H_TOT * NKPAD) return;
    int h = idx / NKPAD;
    int k = idx - h * NKPAD;
    float v = (k < NK) ? W[h * NK + k] : 0.0f;
    int ntile = h >> 3, col = h & 7, kc = k >> 3, kin = k & 7;
    int lane = col * 4 + (kin & 3), breg = kin >> 2;
    Wfrag[((ntile * NKC + kc) * 32 + lane) * 2 + breg] = tf32r(v);
}

// ---------------- main fused kernel ----------------
__global__ __launch_bounds__(NTHREADS, 2)
void sph_mma_kernel(const float* __restrict__ x,
                    const float* __restrict__ bvec,
                    float* __restrict__ out) {
    extern __shared__ float Afrag[];
    const int tid = threadIdx.x;
    const int lane = tid & 31;
    const int wid = tid >> 5;
    const int pbase = blockIdx.x * TILE_P;

    // ---- generate Y for 128 pixels, scattered into A-fragment layout ----
    if (tid < TILE_P) {
        float2 tp = ((const float2*)x)[pbase + tid];
        const float theta = tp.x, phi = tp.y;
        const float ct = cosf(phi);
        const float st = sqrtf(fmaxf(1.0f - ct * ct, 0.0f));
        float pmm = 0.28209479177387814f;                 // sqrt(1/4pi)
        Afrag[a_off(tid, 64)] = tf32r(1.7320508075688772f * ct * pmm);
        const float cth = cosf(theta), sth = sinf(theta);
        float cm = 1.0f, sm = 0.0f;
        #pragma unroll 1
        for (int m = 1; m <= 64; ++m) {
            pmm *= -sqrtf((2.0f * m + 1.0f) / (2.0f * m)) * st;
            float c2 = cm * cth - sm * sth;
            float s2 = sm * cth + cm * sth;
            cm = c2; sm = s2;
            float v = sqrtf(2.0f * m + 3.0f) * ct * pmm;
            v = (m & 1) ? (-1.41421356237309515f * v) : (1.41421356237309515f * v);
            Afrag[a_off(tid, 64 + m)] = tf32r(v * cm);
            Afrag[a_off(tid, 64 - m)] = tf32r(v * sm);
        }
        #pragma unroll
        for (int k = NK; k < NKPAD; ++k) Afrag[a_off(tid, k)] = 0.0f;
    }
    __syncthreads();

    const int wm = (wid & 1) * 4;          // mtile base (4 mtiles = 64 rows)
    const int wnt = (wid >> 1) * 4;        // ntile base within h-tile (4 = 32 h)
    const float4* A4 = (const float4*)Afrag;

    #pragma unroll 1
    for (int ht = 0; ht < NTILES_H; ++ht) {
        const int nt0 = ht * 16 + wnt;

        float acc[4][4][4];
        #pragma unroll
        for (int mt = 0; mt < 4; ++mt)
            #pragma unroll
            for (int nt = 0; nt < 4; ++nt)
                #pragma unroll
                for (int i = 0; i < 4; ++i) acc[mt][nt][i] = 0.0f;

        float2 bcur[4], bnext[4];
        #pragma unroll
        for (int nt = 0; nt < 4; ++nt)
            bcur[nt] = *(const float2*)&Wfrag[(((nt0 + nt) * NKC) * 32 + lane) * 2];

        #pragma unroll 1
        for (int kc = 0; kc < NKC; ++kc) {
            if (kc + 1 < NKC) {
                #pragma unroll
                for (int nt = 0; nt < 4; ++nt)
                    bnext[nt] = *(const float2*)
                        &Wfrag[(((nt0 + nt) * NKC + kc + 1) * 32 + lane) * 2];
            }
            float4 a[4];
            #pragma unroll
            for (int mt = 0; mt < 4; ++mt)
                a[mt] = A4[((wm + mt) * NKC + kc) * 32 + (lane & 3) * 8 + (lane >> 2)];
            #pragma unroll
            for (int mt = 0; mt < 4; ++mt)
                #pragma unroll
                for (int nt = 0; nt < 4; ++nt)
                    mma8(a[mt], bcur[nt], acc[mt][nt]);
            #pragma unroll
            for (int nt = 0; nt < 4; ++nt) bcur[nt] = bnext[nt];
        }

        // ---- epilogue: bias + store (float2 per mma tile row) ----
        const int r = lane >> 2;
        const int cc = (lane & 3) * 2;
        #pragma unroll
        for (int nt = 0; nt < 4; ++nt) {
            const int h0 = (nt0 + nt) * 8 + cc;
            float2 bb = *(const float2*)&bvec[h0];
            #pragma unroll
            for (int mt = 0; mt < 4; ++mt) {
                const int p0 = pbase + (wm + mt) * 16 + r;
                float2 o0 = make_float2(acc[mt][nt][0] + bb.x,
                                        acc[mt][nt][1] + bb.y);
                float2 o1 = make_float2(acc[mt][nt][2] + bb.x,
                                        acc[mt][nt][3] + bb.y);
                *(float2*)&out[(size_t)p0 * H_TOT + h0] = o0;
                *(float2*)&out[(size_t)(p0 + 8) * H_TOT + h0] = o1;
            }
        }
    }
}

extern "C" void kernel_launch(void* const* d_in, const int* in_sizes, int n_in,
                              void* d_out, int out_size) {
    const float* x = (const float*)d_in[0];   // (4,128,256,1,2) -> (P, 2)
    const float* W = (const float*)d_in[1];   // (1024, 129)
    const float* b = (const float*)d_in[2];   // (1024,)
    float* out = (float*)d_out;               // (P, 1024)

    const int P = in_sizes[0] / 2;            // 131072

    wfrag_kernel<<<(H_TOT * NKPAD + 255) / 256, 256>>>(W);

    cudaFuncSetAttribute(sph_mma_kernel,
                         cudaFuncAttributeMaxDynamicSharedMemorySize, SMEM_BYTES);
    sph_mma_kernel<<<P / TILE_P, NTHREADS, SMEM_BYTES>>>(x, b, out);
}